// round 7
// baseline (speedup 1.0000x reference)
#include <cuda_runtime.h>
#include <cuda_fp16.h>
#include <math.h>

#define H 256
#define NB_CLASSES 7
#define B_MAX 14000
#define N_MAX 100000
#define EPS 1e-8f

// Scratch (allocation-free rule: __device__ globals)
__device__ __align__(16) __half g_eh[(size_t)N_MAX * H];  // fp16 embeds (51.2 MB)
__device__ float g_n1[N_MAX];                             // ||e * w_nb||^2
__device__ float g_n2[N_MAX];                             // ||e * w_nb2||^2
__device__ __align__(16) __half g_rr[(size_t)B_MAX * H];  // rawret fp16 (7.2 MB)
__device__ float g_rn[B_MAX];
__device__ __align__(8) float g_csum[NB_CLASSES * H];
__device__ float g_ccnt[NB_CLASSES];

__device__ __forceinline__ float wred_sum(float v) {
    #pragma unroll
    for (int o = 16; o; o >>= 1) v += __shfl_xor_sync(0xFFFFFFFFu, v, o);
    return v;
}

// ---------------------------------------------------------------------------
// Kernel C: fp32 -> fp16 table + per-row weighted norms. Warp per row.
// Block 0 also zeroes the class accumulators.
// ---------------------------------------------------------------------------
__global__ void kc(const float* __restrict__ embeds,
                   const float* __restrict__ wnb,
                   const float* __restrict__ wnb2,
                   int N) {
    if (blockIdx.x == 0) {
        for (int j = threadIdx.x; j < NB_CLASSES * H; j += blockDim.x) g_csum[j] = 0.f;
        if (threadIdx.x < NB_CLASSES) g_ccnt[threadIdx.x] = 0.f;
    }
    const int lane = threadIdx.x & 31;
    const int gw = (blockIdx.x * blockDim.x + threadIdx.x) >> 5;
    const int nw = (gridDim.x * blockDim.x) >> 5;

    const float4 wa0 = ((const float4*)wnb)[2 * lane];
    const float4 wa1 = ((const float4*)wnb)[2 * lane + 1];
    const float4 wb0 = ((const float4*)wnb2)[2 * lane];
    const float4 wb1 = ((const float4*)wnb2)[2 * lane + 1];
    float wav[8] = {wa0.x, wa0.y, wa0.z, wa0.w, wa1.x, wa1.y, wa1.z, wa1.w};
    float wbv[8] = {wb0.x, wb0.y, wb0.z, wb0.w, wb1.x, wb1.y, wb1.z, wb1.w};

    for (int r = gw; r < N; r += nw) {
        const float4* src = (const float4*)(embeds + (size_t)r * H);
        const float4 a = src[2 * lane];
        const float4 b = src[2 * lane + 1];
        float e[8] = {a.x, a.y, a.z, a.w, b.x, b.y, b.z, b.w};

        float n1 = 0.f, n2 = 0.f;
        #pragma unroll
        for (int i = 0; i < 8; i++) {
            const float x1 = e[i] * wav[i];
            const float x2 = e[i] * wbv[i];
            n1 = fmaf(x1, x1, n1);
            n2 = fmaf(x2, x2, n2);
        }

        union { uint4 u; __half2 h[4]; } pk;
        #pragma unroll
        for (int i = 0; i < 4; i++)
            pk.h[i] = __float22half2_rn(make_float2(e[2 * i], e[2 * i + 1]));
        ((uint4*)(g_eh + (size_t)r * H))[lane] = pk.u;

        #pragma unroll
        for (int o = 16; o; o >>= 1) {
            n1 += __shfl_xor_sync(0xFFFFFFFFu, n1, o);
            n2 += __shfl_xor_sync(0xFFFFFFFFu, n2, o);
        }
        if (lane == 0) { g_n1[r] = n1; g_n2[r] = n2; }
    }
}

// ---------------------------------------------------------------------------
// Kernel 1 (K1=16, K2=32): 1 CTA per row b, 256 threads (8 warps).
// Rows gathered by LDG.128 into REGISTERS (no SMEM round trip).
// Warp w owns rows k = w + 8*j, j=0..5 (j<2 -> 1-hop / w_nb).
// Per-warp redundant softmax; register weighted partials; SMEM only for the
// 8-way cross-warp combine (16 KB) + center + dots.
// ---------------------------------------------------------------------------
template<int K1, int K2>
__global__ void __launch_bounds__(256, 3)
k1s(const float* __restrict__ wself,
    const float* __restrict__ wnb,
    const float* __restrict__ wnb2,
    const int* __restrict__ idx,
    const int* __restrict__ labels,
    const int* __restrict__ nbr,
    const int* __restrict__ nbr2) {
    constexpr int KT = K1 + K2;   // 48
    constexpr int JP = KT / 8;    // 6 rows per warp
    constexpr int J1 = K1 / 8;    // 2: first J1 j's are 1-hop

    __shared__ float cen[H];
    __shared__ float nrm_s[KT];
    __shared__ float dots[KT];
    __shared__ float part1[8][H];   // 8 KB: 1-hop partials per warp
    __shared__ float part2[8][H];   // 8 KB: 2-hop partials per warp
    __shared__ float red[8];

    const int b    = blockIdx.x;
    const int tid  = threadIdx.x;
    const int lane = tid & 31;
    const int warp = tid >> 5;

    // --- issue neighbor gathers ASAP (indices are warp-uniform broadcasts) ---
    int rows[JP];
    #pragma unroll
    for (int j = 0; j < JP; j++) {
        const int k = warp + 8 * j;
        rows[j] = (j < J1) ? __ldg(&nbr[b * K1 + k]) : __ldg(&nbr2[b * K2 + k - K1]);
    }
    uint4 raw[JP];
    #pragma unroll
    for (int j = 0; j < JP; j++)
        raw[j] = ((const uint4*)(g_eh + (size_t)rows[j] * H))[lane];

    // --- meanwhile: center (from fp16 table) + norms staging ---
    const int crow = idx[b];
    const float cv = __half2float(g_eh[(size_t)crow * H + tid]) * wself[tid];
    cen[tid] = cv;
    float cs = wred_sum(cv * cv);
    if (lane == 0) red[warp] = cs;

    if (tid < KT) {
        const int r = (tid < K1) ? nbr[b * K1 + tid] : nbr2[b * K2 + tid - K1];
        nrm_s[tid] = (tid < K1) ? g_n1[r] : g_n2[r];
    }
    __syncthreads();

    const float cn = fmaxf(sqrtf(red[0] + red[1] + red[2] + red[3]
                                + red[4] + red[5] + red[6] + red[7]), EPS);

    // per-lane center slices with prompt weights folded in
    float c1v[8], c2v[8];
    {
        const float4 ca = ((const float4*)cen)[2 * lane];
        const float4 cb = ((const float4*)cen)[2 * lane + 1];
        const float ce[8] = {ca.x, ca.y, ca.z, ca.w, cb.x, cb.y, cb.z, cb.w};
        const float4 wa0 = ((const float4*)wnb)[2 * lane];
        const float4 wa1 = ((const float4*)wnb)[2 * lane + 1];
        const float4 wb0 = ((const float4*)wnb2)[2 * lane];
        const float4 wb1 = ((const float4*)wnb2)[2 * lane + 1];
        const float wav[8] = {wa0.x, wa0.y, wa0.z, wa0.w, wa1.x, wa1.y, wa1.z, wa1.w};
        const float wbv[8] = {wb0.x, wb0.y, wb0.z, wb0.w, wb1.x, wb1.y, wb1.z, wb1.w};
        #pragma unroll
        for (int i = 0; i < 8; i++) {
            c1v[i] = ce[i] * wav[i];
            c2v[i] = ce[i] * wbv[i];
        }
    }

    // --- dots from registers ---
    float d[JP];
    #pragma unroll
    for (int j = 0; j < JP; j++) {
        union { uint4 u; __half2 h[4]; } pk;
        pk.u = raw[j];
        const float* cw = (j < J1) ? c1v : c2v;
        const float2 v0 = __half22float2(pk.h[0]);
        const float2 v1 = __half22float2(pk.h[1]);
        const float2 v2 = __half22float2(pk.h[2]);
        const float2 v3 = __half22float2(pk.h[3]);
        d[j] = v0.x * cw[0] + v0.y * cw[1] + v1.x * cw[2] + v1.y * cw[3]
             + v2.x * cw[4] + v2.y * cw[5] + v3.x * cw[6] + v3.y * cw[7];
    }
    #pragma unroll
    for (int o = 16; o; o >>= 1) {
        #pragma unroll
        for (int j = 0; j < JP; j++)
            d[j] += __shfl_xor_sync(0xFFFFFFFFu, d[j], o);
    }
    if (lane == 0) {
        #pragma unroll
        for (int j = 0; j < JP; j++) dots[warp + 8 * j] = d[j];
    }
    __syncthreads();

    // --- per-warp redundant softmax over the 48 cosines ---
    float wj[JP];
    {
        const int ka = lane, kb = lane + 32;
        const float cosA = dots[ka] / (cn * fmaxf(sqrtf(nrm_s[ka]), EPS));
        const float cosB = (kb < KT)
            ? dots[kb] / (cn * fmaxf(sqrtf(nrm_s[kb]), EPS)) : -1e30f;
        float m = fmaxf(cosA, cosB);
        #pragma unroll
        for (int o = 16; o; o >>= 1) m = fmaxf(m, __shfl_xor_sync(0xFFFFFFFFu, m, o));
        const float eA = __expf(cosA - m);
        const float eB = (kb < KT) ? __expf(cosB - m) : 0.f;
        const float inv = 1.f / wred_sum(eA + eB);
        // extract this warp's 6 weights (k = warp + 8j is warp-uniform)
        #pragma unroll
        for (int j = 0; j < JP; j++) {
            const int k = warp + 8 * j;
            const float e = (k < 32)
                ? __shfl_sync(0xFFFFFFFFu, eA, k)
                : __shfl_sync(0xFFFFFFFFu, eB, k - 32);
            wj[j] = e * inv;
        }
    }

    // --- weighted partials from registers (1-hop / 2-hop separated) ---
    float a1[8] = {0, 0, 0, 0, 0, 0, 0, 0};
    float a2[8] = {0, 0, 0, 0, 0, 0, 0, 0};
    #pragma unroll
    for (int j = 0; j < JP; j++) {
        union { uint4 u; __half2 h[4]; } pk;
        pk.u = raw[j];
        float v[8];
        const float2 v0 = __half22float2(pk.h[0]);
        const float2 v1 = __half22float2(pk.h[1]);
        const float2 v2 = __half22float2(pk.h[2]);
        const float2 v3 = __half22float2(pk.h[3]);
        v[0] = v0.x; v[1] = v0.y; v[2] = v1.x; v[3] = v1.y;
        v[4] = v2.x; v[5] = v2.y; v[6] = v3.x; v[7] = v3.y;
        float* acc = (j < J1) ? a1 : a2;
        #pragma unroll
        for (int i = 0; i < 8; i++) acc[i] = fmaf(wj[j], v[i], acc[i]);
    }
    #pragma unroll
    for (int i = 0; i < 2; i++) {
        ((float4*)&part1[warp][8 * lane])[i] =
            make_float4(a1[4 * i], a1[4 * i + 1], a1[4 * i + 2], a1[4 * i + 3]);
        ((float4*)&part2[warp][8 * lane])[i] =
            make_float4(a2[4 * i], a2[4 * i + 1], a2[4 * i + 2], a2[4 * i + 3]);
    }
    __syncthreads();

    // --- final per-channel combine (thread = channel tid) ---
    float A = 0.f, B2 = 0.f;
    #pragma unroll
    for (int w = 0; w < 8; w++) {
        A  += part1[w][tid];
        B2 += part2[w][tid];
    }
    const float r = A * __ldg(&wnb[tid]) + B2 * __ldg(&wnb2[tid]) + cv;

    g_rr[(size_t)b * H + tid] = __float2half(r);

    float rs = wred_sum(r * r);
    if (lane == 0) red[warp] = rs;
    __syncthreads();
    if (tid == 0)
        g_rn[b] = fmaxf(sqrtf(red[0] + red[1] + red[2] + red[3]
                            + red[4] + red[5] + red[6] + red[7]), EPS);

    const int lbl = labels[b];
    atomicAdd(&g_csum[lbl * H + tid], r);
    if (tid == 0) atomicAdd(&g_ccnt[lbl], 1.f);
}

// ---------------------------------------------------------------------------
// Generic fallback (any K1/K2), fp32 path
// ---------------------------------------------------------------------------
__global__ void kzf() {
    int i = blockIdx.x * blockDim.x + threadIdx.x;
    if (i < NB_CLASSES * H) g_csum[i] = 0.f;
    if (i < NB_CLASSES) g_ccnt[i] = 0.f;
}

__global__ void k1g(const float* __restrict__ embeds,
                    const float* __restrict__ wself,
                    const float* __restrict__ wnb,
                    const float* __restrict__ wnb2,
                    const int* __restrict__ idx,
                    const int* __restrict__ labels,
                    const int* __restrict__ nbr,
                    const int* __restrict__ nbr2,
                    int K1, int K2) {
    extern __shared__ float sh[];
    const int KT = K1 + K2;
    float* nb_s = sh;
    float* cen  = sh + KT * H;
    float* dots = cen + H;
    float* nrms = dots + KT;
    float* wgt  = nrms + KT;
    float* red  = wgt + KT;

    const int b    = blockIdx.x;
    const int tid  = threadIdx.x;
    const int lane = tid & 31;
    const int warp = tid >> 5;

    const int crow = idx[b];
    const float c = embeds[(size_t)crow * H + tid] * wself[tid];
    cen[tid] = c;
    float cs = wred_sum(c * c);
    if (lane == 0) red[warp] = cs;
    __syncthreads();

    float cn = 0.f;
    #pragma unroll
    for (int i = 0; i < 8; i++) cn += red[i];
    cn = fmaxf(sqrtf(cn), EPS);

    const float4* cen4 = (const float4*)cen;
    const float4 c0 = cen4[lane];
    const float4 c1 = cen4[lane + 32];

    for (int k = warp; k < KT; k += 8) {
        const int r = (k < K1) ? nbr[b * K1 + k] : nbr2[b * K2 + (k - K1)];
        const float4* src = (const float4*)(embeds + (size_t)r * H);
        const float4* wv  = (const float4*)((k < K1) ? wnb : wnb2);
        float4 e0 = src[lane];
        float4 e1 = src[lane + 32];
        const float4 w0 = wv[lane];
        const float4 w1 = wv[lane + 32];
        e0.x *= w0.x; e0.y *= w0.y; e0.z *= w0.z; e0.w *= w0.w;
        e1.x *= w1.x; e1.y *= w1.y; e1.z *= w1.z; e1.w *= w1.w;

        float d = e0.x * c0.x + e0.y * c0.y + e0.z * c0.z + e0.w * c0.w
                + e1.x * c1.x + e1.y * c1.y + e1.z * c1.z + e1.w * c1.w;
        float s = e0.x * e0.x + e0.y * e0.y + e0.z * e0.z + e0.w * e0.w
                + e1.x * e1.x + e1.y * e1.y + e1.z * e1.z + e1.w * e1.w;

        float4* dst = (float4*)(nb_s + k * H);
        dst[lane]      = e0;
        dst[lane + 32] = e1;

        d = wred_sum(d);
        s = wred_sum(s);
        if (lane == 0) { dots[k] = d; nrms[k] = s; }
    }
    __syncthreads();

    if (warp == 0) {
        const int ka = lane, kb = lane + 32;
        float cosA = -1e30f, cosB = -1e30f;
        if (ka < KT) cosA = dots[ka] / (cn * fmaxf(sqrtf(nrms[ka]), EPS));
        if (kb < KT) cosB = dots[kb] / (cn * fmaxf(sqrtf(nrms[kb]), EPS));
        float m = fmaxf(cosA, cosB);
        #pragma unroll
        for (int o = 16; o; o >>= 1) m = fmaxf(m, __shfl_xor_sync(0xFFFFFFFFu, m, o));
        float eA = (ka < KT) ? __expf(cosA - m) : 0.f;
        float eB = (kb < KT) ? __expf(cosB - m) : 0.f;
        const float inv = 1.f / wred_sum(eA + eB);
        if (ka < KT) wgt[ka] = eA * inv;
        if (kb < KT) wgt[kb] = eB * inv;
    }
    __syncthreads();

    float acc = 0.f;
    for (int k = 0; k < KT; k++)
        acc = fmaf(wgt[k], nb_s[k * H + tid], acc);
    const float rr = acc + c;

    g_rr[(size_t)b * H + tid] = __float2half(rr);

    float rs = wred_sum(rr * rr);
    __syncthreads();
    if (lane == 0) red[warp] = rs;
    __syncthreads();
    if (tid == 0) {
        float t = 0.f;
        #pragma unroll
        for (int i = 0; i < 8; i++) t += red[i];
        g_rn[b] = fmaxf(sqrtf(t), EPS);
    }

    const int lbl = labels[b];
    atomicAdd(&g_csum[lbl * H + tid], rr);
    if (tid == 0) atomicAdd(&g_ccnt[lbl], 1.f);
}

// ---------------------------------------------------------------------------
// Kernel 3: output (class means fused). 128 threads; warp = 8 rows.
// ---------------------------------------------------------------------------
__global__ void __launch_bounds__(128)
k3(float* __restrict__ out, int B) {
    const int tid  = threadIdx.x;
    const int lane = tid & 31;
    const int warp = tid >> 5;

    float4 av0[NB_CLASSES], av1[NB_CLASSES];
    float an_r[NB_CLASSES];
    #pragma unroll
    for (int cc = 0; cc < NB_CLASSES; cc++) {
        const float inv_cnt = 1.f / fmaxf(g_ccnt[cc], 1.f);
        float4 a = ((const float4*)(g_csum + cc * H))[2 * lane];
        float4 b = ((const float4*)(g_csum + cc * H))[2 * lane + 1];
        a.x *= inv_cnt; a.y *= inv_cnt; a.z *= inv_cnt; a.w *= inv_cnt;
        b.x *= inv_cnt; b.y *= inv_cnt; b.z *= inv_cnt; b.w *= inv_cnt;
        av0[cc] = a; av1[cc] = b;
        an_r[cc] = a.x * a.x + a.y * a.y + a.z * a.z + a.w * a.w
                 + b.x * b.x + b.y * b.y + b.z * b.z + b.w * b.w;
    }
    #pragma unroll
    for (int o = 16; o; o >>= 1) {
        #pragma unroll
        for (int cc = 0; cc < NB_CLASSES; cc++)
            an_r[cc] += __shfl_xor_sync(0xFFFFFFFFu, an_r[cc], o);
    }
    #pragma unroll
    for (int cc = 0; cc < NB_CLASSES; cc++)
        an_r[cc] = fmaxf(sqrtf(an_r[cc]), EPS);

    const int base = blockIdx.x * 32 + warp * 8;
    #pragma unroll
    for (int i = 0; i < 8; i++) {
        const int b = base + i;
        if (b >= B) return;

        union { uint4 u; __half2 h[4]; } pk;
        pk.u = ((const uint4*)(g_rr + (size_t)b * H))[lane];
        const float2 v0 = __half22float2(pk.h[0]);
        const float2 v1 = __half22float2(pk.h[1]);
        const float2 v2 = __half22float2(pk.h[2]);
        const float2 v3 = __half22float2(pk.h[3]);

        float d[NB_CLASSES];
        #pragma unroll
        for (int cc = 0; cc < NB_CLASSES; cc++) {
            d[cc] = v0.x * av0[cc].x + v0.y * av0[cc].y
                  + v1.x * av0[cc].z + v1.y * av0[cc].w
                  + v2.x * av1[cc].x + v2.y * av1[cc].y
                  + v3.x * av1[cc].z + v3.y * av1[cc].w;
        }
        #pragma unroll
        for (int o = 16; o; o >>= 1) {
            #pragma unroll
            for (int cc = 0; cc < NB_CLASSES; cc++)
                d[cc] += __shfl_xor_sync(0xFFFFFFFFu, d[cc], o);
        }

        const float rbn = g_rn[b];
        float m = -1e30f;
        #pragma unroll
        for (int cc = 0; cc < NB_CLASSES; cc++) {
            d[cc] = d[cc] / (rbn * an_r[cc]);
            m = fmaxf(m, d[cc]);
        }
        float s = 0.f;
        #pragma unroll
        for (int cc = 0; cc < NB_CLASSES; cc++) {
            d[cc] = __expf(d[cc] - m);
            s += d[cc];
        }
        const float inv = 1.f / s;
        if (lane < NB_CLASSES) {
            float v = 0.f;
            #pragma unroll
            for (int cc = 0; cc < NB_CLASSES; cc++)
                if (lane == cc) v = d[cc] * inv;
            out[b * NB_CLASSES + lane] = v;
        }
    }
}

// ---------------------------------------------------------------------------
extern "C" void kernel_launch(void* const* d_in, const int* in_sizes, int n_in,
                              void* d_out, int out_size) {
    const float* embeds = (const float*)d_in[0];
    const float* wself  = (const float*)d_in[1];
    const float* wnb    = (const float*)d_in[2];
    const float* wnb2   = (const float*)d_in[3];
    const int*   idx    = (const int*)d_in[4];
    const int*   labels = (const int*)d_in[5];
    const int*   nbr    = (const int*)d_in[6];
    const int*   nbr2   = (const int*)d_in[7];
    float* out = (float*)d_out;

    const int B  = in_sizes[4];
    const int K1 = in_sizes[6] / B;
    const int K2 = in_sizes[7] / B;
    const int KT = K1 + K2;
    const int N  = in_sizes[0] / H;

    if (K1 == 16 && K2 == 32 && N <= N_MAX && B <= B_MAX) {
        kc<<<2048, 256>>>(embeds, wnb, wnb2, N);
        k1s<16, 32><<<B, 256>>>(wself, wnb, wnb2, idx, labels, nbr, nbr2);
    } else {
        const size_t smem = (size_t)(KT * H + H + 3 * KT + 32) * sizeof(float);
        cudaFuncSetAttribute(k1g, cudaFuncAttributeMaxDynamicSharedMemorySize, (int)smem);
        kzf<<<NB_CLASSES, 256>>>();
        k1g<<<B, 256, smem>>>(embeds, wself, wnb, wnb2, idx, labels, nbr, nbr2, K1, K2);
    }
    k3<<<(B + 31) / 32, 128>>>(out, B);
}